// round 7
// baseline (speedup 1.0000x reference)
#include <cuda_runtime.h>

// Grouped 1x7 conv (NCHW, groups=2, identical weights per group) + roll(H),
// as a per-(group,row) GEMM on tensor cores with 3xTF32 precision recovery.
//
// C[96,56] = A[96,168] x B[168,56]:
//   A[oc][k] = w[ic][oc][kw],  B[k][w] = x[ic][h][w+kw-3],  k = kw*24 + ic.
// Block = (h, g): 6 warps, warp wid = m-tile (16 oc) x 56 pixels (7 n-frags).
// smem holds A and the padded x row, both split to (tf32_hi, tf32_lo) uint2.
// Strides 172 / 68 u64 make every fragment LDS.64 bank-conflict-free.

#define Hdim 56
#define Wdim 56
#define HW   3136
#define ICg  24
#define KW   7
#define SWS  172   // u64 stride per A row (168 used)
#define SXS  68    // u64 stride per x ic (62 used)

__device__ __forceinline__ unsigned tf32_rna(float x) {
    unsigned r;
    asm("cvt.rna.tf32.f32 %0, %1;" : "=r"(r) : "f"(x));
    return r;
}

__device__ __forceinline__ void mma_tf32(float c[4],
                                         unsigned a0, unsigned a1,
                                         unsigned a2, unsigned a3,
                                         unsigned b0, unsigned b1) {
    asm volatile(
        "mma.sync.aligned.m16n8k8.row.col.f32.tf32.tf32.f32 "
        "{%0,%1,%2,%3},{%4,%5,%6,%7},{%8,%9},{%0,%1,%2,%3};"
        : "+f"(c[0]), "+f"(c[1]), "+f"(c[2]), "+f"(c[3])
        : "r"(a0), "r"(a1), "r"(a2), "r"(a3), "r"(b0), "r"(b1));
}

__global__ __launch_bounds__(192, 1)
void conv1x7_tc(const float* __restrict__ x, const float* __restrict__ w,
                const int* __restrict__ shift, float* __restrict__ out)
{
    extern __shared__ char smem[];
    uint2* sw = (uint2*)smem;                              // [96][SWS]
    uint2* sx = (uint2*)(smem + 96 * SWS * 8);             // [24][SXS]

    const int tid = threadIdx.x;
    const int h   = blockIdx.x;
    const int g   = blockIdx.y;

    // ---- stage + split weights: sw[oc][kw*24+ic] = split(w[ic][oc][kw]) ----
    for (int i = tid; i < ICg * 96 * KW; i += 192) {       // 16128, coalesced read
        int ic = i / 672;
        int r  = i - ic * 672;
        int oc = r / 7;
        int kw = r - oc * 7;
        float v = w[i];
        unsigned hi = tf32_rna(v);
        float lo = v - __uint_as_float(hi);
        sw[oc * SWS + kw * ICg + ic] = make_uint2(hi, tf32_rna(lo));
    }

    // ---- stage + split padded x row: sx[ic][p] = split(x[ic][h][p-3]) ----
    const float* xrow = x + (size_t)g * (ICg * HW) + h * Wdim;
    for (int i = tid; i < ICg * 64; i += 192) {
        int ic = i >> 6;
        int p  = i & 63;
        int wc = p - 3;
        float v = (wc >= 0 && wc < Wdim) ? xrow[ic * HW + wc] : 0.f;
        unsigned hi = tf32_rna(v);
        float lo = v - __uint_as_float(hi);
        sx[ic * SXS + p] = make_uint2(hi, tf32_rna(lo));
    }
    __syncthreads();

    const int wid  = tid >> 5;        // m-tile 0..5
    const int lane = tid & 31;
    const int lg   = lane >> 2;       // 0..7
    const int lk   = lane & 3;        // 0..3

    const uint2* Abase = sw + (wid * 16 + lg) * SWS + lk;

    float c[7][4];
    #pragma unroll
    for (int nt = 0; nt < 7; nt++)
        #pragma unroll
        for (int j = 0; j < 4; j++) c[nt][j] = 0.f;

    #pragma unroll 1
    for (int kw = 0; kw < KW; kw++) {
        #pragma unroll
        for (int ics = 0; ics < 3; ics++) {        // 21 k-steps of 8
            const int kb = kw * ICg + ics * 8;
            uint2 A0 = Abase[kb];
            uint2 A1 = Abase[kb + 8 * SWS];
            uint2 A2 = Abase[kb + 4];
            uint2 A3 = Abase[kb + 4 + 8 * SWS];

            const uint2* xb0 = sx + (ics * 8 + lk) * SXS + lg + kw;
            const uint2* xb1 = xb0 + 4 * SXS;

            uint2 B0[7], B1[7];
            #pragma unroll
            for (int nt = 0; nt < 7; nt++) {
                B0[nt] = xb0[nt * 8];
                B1[nt] = xb1[nt * 8];
            }

            // 3xTF32: hh, hl, lh — each wave of 7 MMAs is independent
            #pragma unroll
            for (int nt = 0; nt < 7; nt++)
                mma_tf32(c[nt], A0.x, A1.x, A2.x, A3.x, B0[nt].x, B1[nt].x);
            #pragma unroll
            for (int nt = 0; nt < 7; nt++)
                mma_tf32(c[nt], A0.x, A1.x, A2.x, A3.x, B0[nt].y, B1[nt].y);
            #pragma unroll
            for (int nt = 0; nt < 7; nt++)
                mma_tf32(c[nt], A0.y, A1.y, A2.y, A3.y, B0[nt].x, B1[nt].x);
        }
    }

    // ---- roll + store: c0/c1 -> (row, 2lk..2lk+1), c2/c3 -> row+8 ----
    const int s = *shift;
    int ho = (h + s) % Hdim;
    if (ho < 0) ho += Hdim;

    float* ob = out + (size_t)(g * 96 + wid * 16 + lg) * HW + ho * Wdim + 2 * lk;
    #pragma unroll
    for (int nt = 0; nt < 7; nt++) {
        *(float2*)(ob + nt * 8)          = make_float2(c[nt][0], c[nt][1]);
        *(float2*)(ob + 8 * HW + nt * 8) = make_float2(c[nt][2], c[nt][3]);
    }
}

extern "C" void kernel_launch(void* const* d_in, const int* in_sizes, int n_in,
                              void* d_out, int out_size)
{
    const float* x     = (const float*)d_in[0];
    const float* w     = (const float*)d_in[1];
    const int*   shift = (const int*)  d_in[2];
    float*       out   = (float*)d_out;

    const int smem_bytes = 96 * SWS * 8 + ICg * SXS * 8;   // 132096 + 13056 = 145152
    cudaFuncSetAttribute(conv1x7_tc,
                         cudaFuncAttributeMaxDynamicSharedMemorySize, smem_bytes);

    dim3 grid(Hdim, 2);   // 56 rows x 2 groups = 112 blocks
    conv1x7_tc<<<grid, 192, smem_bytes>>>(x, w, shift, out);
}

// round 8
// speedup vs baseline: 1.2608x; 1.2608x over previous
#include <cuda_runtime.h>

// Grouped 1x7 conv (NCHW, groups=2, shared weights) + roll(H), on tensor cores
// (m16n8k8 tf32, 3xTF32 precision recovery).
//
// Kernel 1: one-time split of w into (tf32_hi, tf32_lo) uint2 in __device__
//           scratch, laid out [oc][kw*24+ic] with padded stride SWS=172 so
//           kernel 2 stages weights with a pure linear uint4 copy.
// Kernel 2: block=(h,g); 12 warps = (m-tile 0..5) x (n-half 0/1).
//           n-halves cover frags 0-3 and 3-6 (frag 3 duplicated, benign).

#define Hdim 56
#define Wdim 56
#define HW   3136
#define ICg  24
#define KW   7
#define SWS  172   // u64 stride per A row (168 used)
#define SXS  68    // u64 stride per x ic (62 used)

__device__ uint2 g_wsplit[96 * SWS];   // 132 KB scratch, layout matches smem

__device__ __forceinline__ unsigned tf32_rna(float x) {
    unsigned r;
    asm("cvt.rna.tf32.f32 %0, %1;" : "=r"(r) : "f"(x));
    return r;
}

__device__ __forceinline__ void mma_tf32(float c[4],
                                         unsigned a0, unsigned a1,
                                         unsigned a2, unsigned a3,
                                         unsigned b0, unsigned b1) {
    asm volatile(
        "mma.sync.aligned.m16n8k8.row.col.f32.tf32.tf32.f32 "
        "{%0,%1,%2,%3},{%4,%5,%6,%7},{%8,%9},{%0,%1,%2,%3};"
        : "+f"(c[0]), "+f"(c[1]), "+f"(c[2]), "+f"(c[3])
        : "r"(a0), "r"(a1), "r"(a2), "r"(a3), "r"(b0), "r"(b1));
}

__global__ __launch_bounds__(256, 4)
void split_w_kernel(const float* __restrict__ w)
{
    int i = blockIdx.x * 256 + threadIdx.x;
    if (i >= ICg * 96 * KW) return;          // 16128
    int ic = i / 672;
    int r  = i - ic * 672;
    int oc = r / 7;
    int kw = r - oc * 7;
    float v = w[i];
    unsigned hi = tf32_rna(v);
    float lo = v - __uint_as_float(hi);
    g_wsplit[oc * SWS + kw * ICg + ic] = make_uint2(hi, tf32_rna(lo));
}

__global__ __launch_bounds__(384, 1)
void conv1x7_tc2(const float* __restrict__ x,
                 const int* __restrict__ shift, float* __restrict__ out)
{
    extern __shared__ char smem[];
    uint2* sw = (uint2*)smem;                              // [96][SWS]
    uint2* sx = (uint2*)(smem + 96 * SWS * 8);             // [24][SXS]

    const int tid = threadIdx.x;
    const int h   = blockIdx.x;
    const int g   = blockIdx.y;

    // ---- weights: pure linear uint4 copy of pre-split scratch ----
    {
        const uint4* src = (const uint4*)g_wsplit;
        uint4*       dst = (uint4*)sw;
        #pragma unroll 4
        for (int i = tid; i < 96 * SWS / 2; i += 384)      // 8256
            dst[i] = src[i];
    }

    // ---- stage + split padded x row: sx[ic][p] = split(x[ic][h][p-3]) ----
    const float* xrow = x + (size_t)g * (ICg * HW) + h * Wdim;
    for (int i = tid; i < ICg * 64; i += 384) {            // 1536
        int ic = i >> 6;
        int p  = i & 63;
        int wc = p - 3;
        float v = (wc >= 0 && wc < Wdim) ? xrow[ic * HW + wc] : 0.f;
        unsigned hi = tf32_rna(v);
        float lo = v - __uint_as_float(hi);
        sx[ic * SXS + p] = make_uint2(hi, tf32_rna(lo));
    }
    __syncthreads();

    const int wid  = tid >> 5;        // 0..11
    const int mt   = wid >> 1;        // m-tile 0..5
    const int nh   = wid & 1;         // n-half
    const int nt0  = nh * 3;          // frags 0..3 or 3..6 (3 duplicated)
    const int lane = tid & 31;
    const int lg   = lane >> 2;       // 0..7
    const int lk   = lane & 3;        // 0..3

    const uint2* Abase = sw + (mt * 16 + lg) * SWS + lk;

    float c[4][4];
    #pragma unroll
    for (int j = 0; j < 4; j++)
        #pragma unroll
        for (int q = 0; q < 4; q++) c[j][q] = 0.f;

    #pragma unroll 1
    for (int kw = 0; kw < KW; kw++) {
        #pragma unroll
        for (int ics = 0; ics < 3; ics++) {        // 21 k-steps of 8
            const int kb = kw * ICg + ics * 8;
            uint2 A0 = Abase[kb];
            uint2 A1 = Abase[kb + 8 * SWS];
            uint2 A2 = Abase[kb + 4];
            uint2 A3 = Abase[kb + 4 + 8 * SWS];

            const uint2* xb0 = sx + (ics * 8 + lk) * SXS + lg + kw + nt0 * 8;
            const uint2* xb1 = xb0 + 4 * SXS;

            uint2 B0[4], B1[4];
            #pragma unroll
            for (int j = 0; j < 4; j++) {
                B0[j] = xb0[j * 8];
                B1[j] = xb1[j * 8];
            }

            // 3xTF32: hh, hl, lh — each wave of 4 MMAs is independent
            #pragma unroll
            for (int j = 0; j < 4; j++)
                mma_tf32(c[j], A0.x, A1.x, A2.x, A3.x, B0[j].x, B1[j].x);
            #pragma unroll
            for (int j = 0; j < 4; j++)
                mma_tf32(c[j], A0.x, A1.x, A2.x, A3.x, B0[j].y, B1[j].y);
            #pragma unroll
            for (int j = 0; j < 4; j++)
                mma_tf32(c[j], A0.y, A1.y, A2.y, A3.y, B0[j].x, B1[j].x);
        }
    }

    // ---- roll + store ----
    const int s = *shift;
    int ho = (h + s) % Hdim;
    if (ho < 0) ho += Hdim;

    float* ob = out + (size_t)(g * 96 + mt * 16 + lg) * HW + ho * Wdim
                    + (nt0 * 8 + 2 * lk);
    #pragma unroll
    for (int j = 0; j < 4; j++) {
        *(float2*)(ob + j * 8)          = make_float2(c[j][0], c[j][1]);
        *(float2*)(ob + 8 * HW + j * 8) = make_float2(c[j][2], c[j][3]);
    }
}

extern "C" void kernel_launch(void* const* d_in, const int* in_sizes, int n_in,
                              void* d_out, int out_size)
{
    const float* x     = (const float*)d_in[0];
    const float* w     = (const float*)d_in[1];
    const int*   shift = (const int*)  d_in[2];
    float*       out   = (float*)d_out;

    split_w_kernel<<<63, 256>>>(w);    // 63*256 = 16128

    const int smem_bytes = 96 * SWS * 8 + ICg * SXS * 8;   // 145152
    cudaFuncSetAttribute(conv1x7_tc2,
                         cudaFuncAttributeMaxDynamicSharedMemorySize, smem_bytes);

    dim3 grid(Hdim, 2);   // 56 rows x 2 groups = 112 blocks
    conv1x7_tc2<<<grid, 384, smem_bytes>>>(x, shift, out);
}